// round 5
// baseline (speedup 1.0000x reference)
#include <cuda_runtime.h>
#include <math.h>
#include <stdint.h>

#define HIDDEN 150
#define EMBED 300
#define OUTC 5
#define DEPTH 13
#define NN 8191          // 2^13 - 1
#define LL 4096          // leaves
#define LEAF_START 4095  // 2^12 - 1
#define BK 20            // 300 = 15 * 20

// ---------------- device scratch (no allocs allowed) ----------------
__device__ float g_H[NN * HIDDEN];
__device__ float g_C[NN * HIDDEN];
// gate-interleaved stacked weights: row n = j*GATES + gate, each row 300 wide
__device__ float g_WLi[450 * EMBED];   // leaf: gates {i,o,u}, GATES=3
__device__ float g_WUi[750 * EMBED];   // inner: gates {i,fl,fr,o,u}, GATES=5
__device__ float g_bLi[450];
__device__ float g_bUi[750];

__device__ __forceinline__ float sigmoidf(float x) {
    return 1.0f / (1.0f + expf(-x));
}

// packed f32x2 FMA: d = a*b + d (elementwise on two packed floats)
__device__ __forceinline__ void ffma2(unsigned long long& d,
                                      unsigned long long a,
                                      unsigned long long b) {
    asm("fma.rn.f32x2 %0, %1, %2, %0;" : "+l"(d) : "l"(a), "l"(b));
}
__device__ __forceinline__ float f2_lo(unsigned long long v) {
    return __uint_as_float((unsigned)(v & 0xffffffffull));
}
__device__ __forceinline__ float f2_hi(unsigned long long v) {
    return __uint_as_float((unsigned)(v >> 32));
}

// ---------------- weight stacking (gate-interleaved) ----------------
__global__ void prep_kernel(
    const float* __restrict__ Wi, const float* __restrict__ bi,
    const float* __restrict__ Wo, const float* __restrict__ bo,
    const float* __restrict__ Wu, const float* __restrict__ bu,
    const float* __restrict__ U0i, const float* __restrict__ U1i, const float* __restrict__ bbi,
    const float* __restrict__ U00f, const float* __restrict__ U01f,
    const float* __restrict__ U10f, const float* __restrict__ U11f, const float* __restrict__ bbf,
    const float* __restrict__ U0o, const float* __restrict__ U1o, const float* __restrict__ bbo,
    const float* __restrict__ U0u, const float* __restrict__ U1u, const float* __restrict__ bbu)
{
    int t = blockIdx.x * blockDim.x + threadIdx.x;
    int stride = gridDim.x * blockDim.x;

    // leaf weights: n = j*3 + g ; g: 0=i, 1=o, 2=u
    for (int idx = t; idx < 450 * EMBED; idx += stride) {
        int n = idx / EMBED, k = idx % EMBED;
        int j = n / 3, g = n % 3;
        const float* W = (g == 0) ? Wi : (g == 1) ? Wo : Wu;
        g_WLi[idx] = W[j * EMBED + k];
    }
    // inner weights: n = j*5 + g ; g: 0=i, 1=fl, 2=fr, 3=o, 4=u ; cols = [U0 | U1]
    for (int idx = t; idx < 750 * EMBED; idx += stride) {
        int n = idx / EMBED, k = idx % EMBED;
        int j = n / 5, g = n % 5;
        const float* U0; const float* U1;
        switch (g) {
            case 0:  U0 = U0i;  U1 = U1i;  break;
            case 1:  U0 = U00f; U1 = U01f; break;
            case 2:  U0 = U10f; U1 = U11f; break;
            case 3:  U0 = U0o;  U1 = U1o;  break;
            default: U0 = U0u;  U1 = U1u;  break;
        }
        g_WUi[idx] = (k < HIDDEN) ? U0[j * HIDDEN + k] : U1[j * HIDDEN + (k - HIDDEN)];
    }
    if (t < 450) {
        int j = t / 3, g = t % 3;
        g_bLi[t] = (g == 0) ? bi[j] : (g == 1) ? bo[j] : bu[j];
    }
    if (t < 750) {
        int j = t / 5, g = t % 5;
        g_bUi[t] = (g == 0) ? bbi[j] : (g <= 2) ? bbf[j] : (g == 3) ? bbo[j] : bbu[j];
    }
}

// ---------------- fused tiled GEMM + activation (f32x2 packed) ----------------
// thread tile: ROWS rows (as ROWS/2 packed pairs) x 1 j x GATES gates
// block: (BM/ROWS)*BJ threads ; tx = tid % BJ -> j ; ty = tid / BJ -> row group
template<int GATES, int MODE, int BM, int BJ, int ROWS>
__global__ __launch_bounds__((BM / ROWS) * BJ)
void fused_level(int s, int M,
                 const float* __restrict__ emb,
                 const int* __restrict__ words)
{
    constexpr int THREADS = (BM / ROWS) * BJ;
    constexpr int WCOLS = BJ * GATES;
    constexpr int AELEMS = BM * BK;
    constexpr int WELEMS = WCOLS * BK;
    constexpr int NT = EMBED / BK;     // 15 k-tiles
    constexpr int RP = ROWS / 2;       // packed row pairs

    __shared__ float  As[BK][BM];
    __shared__ float2 Ws2[BK][WCOLS];  // duplicated: {w, w}
    __shared__ int    rowOff[BM];

    const float* __restrict__ W     = (MODE == 0) ? g_WLi : g_WUi;
    const float* __restrict__ Abase = (MODE == 0) ? emb : (g_H + (2 * s + 1) * HIDDEN);
    const float* __restrict__ bias  = (MODE == 0) ? g_bLi : g_bUi;

    int bm = blockIdx.x * BM;
    int j0 = blockIdx.y * BJ;
    int n0 = j0 * GATES;
    int tid = threadIdx.x;
    int tx = tid % BJ, ty = tid / BJ;

    for (int e = tid; e < BM; e += THREADS) {
        int m = bm + e;
        int off = -1;
        if (m < M) {
            if (MODE == 0) off = words[LEAF_START + m] * EMBED;
            else           off = m * EMBED;   // children [lh|rh] contiguous
        }
        rowOff[e] = off;
    }
    __syncthreads();

    unsigned long long acc[RP][GATES];
    #pragma unroll
    for (int p = 0; p < RP; p++)
        #pragma unroll
        for (int g = 0; g < GATES; g++)
            acc[p][g] = 0ull;

    #pragma unroll 1
    for (int t = 0; t < NT; t++) {
        int k0 = t * BK;
        // load A tile
        #pragma unroll
        for (int e = tid; e < AELEMS; e += THREADS) {
            int ml = e / BK, kk = e % BK;
            int off = rowOff[ml];
            As[kk][ml] = (off >= 0) ? Abase[off + k0 + kk] : 0.0f;
        }
        // load W tile (duplicated halves)
        #pragma unroll
        for (int e = tid; e < WELEMS; e += THREADS) {
            int nl = e / BK, kk = e % BK;
            int n = n0 + nl;
            float w = (n < HIDDEN * GATES) ? W[n * EMBED + k0 + kk] : 0.0f;
            Ws2[kk][nl] = make_float2(w, w);
        }
        __syncthreads();

        #pragma unroll
        for (int kk = 0; kk < BK; kk++) {
            unsigned long long a2[RP], w2[GATES];
            const unsigned long long* ap =
                reinterpret_cast<const unsigned long long*>(&As[kk][ty * ROWS]);
            #pragma unroll
            for (int p = 0; p < RP; p++) a2[p] = ap[p];
            const unsigned long long* wp =
                reinterpret_cast<const unsigned long long*>(&Ws2[kk][tx * GATES]);
            #pragma unroll
            for (int g = 0; g < GATES; g++) w2[g] = wp[g];
            #pragma unroll
            for (int p = 0; p < RP; p++)
                #pragma unroll
                for (int g = 0; g < GATES; g++)
                    ffma2(acc[p][g], a2[p], w2[g]);
        }
        __syncthreads();
    }

    int j = j0 + tx;
    if (j >= HIDDEN) return;
    int nb = j * GATES;
    #pragma unroll
    for (int p = 0; p < RP; p++) {
        #pragma unroll
        for (int half = 0; half < 2; half++) {
            int m = bm + ty * ROWS + p * 2 + half;
            if (m >= M) continue;
            float v[GATES];
            #pragma unroll
            for (int g = 0; g < GATES; g++)
                v[g] = half ? f2_hi(acc[p][g]) : f2_lo(acc[p][g]);
            if (MODE == 0) {
                float ig = sigmoidf(v[0] + bias[nb + 0]);
                float og = sigmoidf(v[1] + bias[nb + 1]);
                float uv = tanhf   (v[2] + bias[nb + 2]);
                float c = ig * uv;
                float h = og * tanhf(c);
                int node = LEAF_START + m;
                g_H[node * HIDDEN + j] = h;
                g_C[node * HIDDEN + j] = c;
            } else {
                float ig = sigmoidf(v[0] + bias[nb + 0]);
                float fl = sigmoidf(v[1] + bias[nb + 1]);
                float fr = sigmoidf(v[2] + bias[nb + 2]);
                float og = sigmoidf(v[3] + bias[nb + 3]);
                float uv = tanhf   (v[4] + bias[nb + 4]);
                int node = s + m;
                float lc = g_C[(2 * node + 1) * HIDDEN + j];
                float rc = g_C[(2 * node + 2) * HIDDEN + j];
                float c = ig * uv + fl * lc + fr * rc;
                float h = og * tanhf(c);
                g_H[node * HIDDEN + j] = h;
                g_C[node * HIDDEN + j] = c;
            }
        }
    }
}

// ---------------- warp-per-(node, j) kernel for tiny levels ----------------
__global__ void warp_level(int s, int M)
{
    int wid  = (blockIdx.x * blockDim.x + threadIdx.x) >> 5;
    int lane = threadIdx.x & 31;
    int m = wid / HIDDEN;
    int j = wid % HIDDEN;
    if (m >= M) return;

    const float* __restrict__ A  = g_H + (2 * s + 1 + 2 * m) * HIDDEN;  // 300 contiguous
    const float* __restrict__ Wr = g_WUi + (j * 5) * EMBED;

    float a0 = 0.f, a1 = 0.f, a2 = 0.f, a3 = 0.f, a4 = 0.f;
    #pragma unroll
    for (int kb = 0; kb < EMBED; kb += 32) {
        int k = kb + lane;
        float a = A[k];
        a0 += a * Wr[k];
        a1 += a * Wr[EMBED + k];
        a2 += a * Wr[2 * EMBED + k];
        a3 += a * Wr[3 * EMBED + k];
        a4 += a * Wr[4 * EMBED + k];
    }
    #pragma unroll
    for (int d = 16; d > 0; d >>= 1) {
        a0 += __shfl_xor_sync(0xffffffff, a0, d);
        a1 += __shfl_xor_sync(0xffffffff, a1, d);
        a2 += __shfl_xor_sync(0xffffffff, a2, d);
        a3 += __shfl_xor_sync(0xffffffff, a3, d);
        a4 += __shfl_xor_sync(0xffffffff, a4, d);
    }
    if (lane == 0) {
        int nb = j * 5;
        float ig = sigmoidf(a0 + g_bUi[nb + 0]);
        float fl = sigmoidf(a1 + g_bUi[nb + 1]);
        float fr = sigmoidf(a2 + g_bUi[nb + 2]);
        float og = sigmoidf(a3 + g_bUi[nb + 3]);
        float uv = tanhf   (a4 + g_bUi[nb + 4]);
        int node = s + m;
        float lc = g_C[(2 * node + 1) * HIDDEN + j];
        float rc = g_C[(2 * node + 2) * HIDDEN + j];
        float c = ig * uv + fl * lc + fr * rc;
        float h = og * tanhf(c);
        g_H[node * HIDDEN + j] = h;
        g_C[node * HIDDEN + j] = c;
    }
}

// ---------------- loss ----------------
__global__ void zero_out(float* out)
{
    if (threadIdx.x == 0 && blockIdx.x == 0) out[0] = 0.0f;
}

__global__ void loss_kernel(const float* __restrict__ Why,
                            const float* __restrict__ by,
                            const int*   __restrict__ scores,
                            float* __restrict__ out)
{
    int gw   = (blockIdx.x * blockDim.x + threadIdx.x) >> 5;
    int lane = threadIdx.x & 31;
    if (gw >= NN) return;

    const float* h = g_H + gw * HIDDEN;
    float logits[OUTC];
    #pragma unroll
    for (int o = 0; o < OUTC; o++) {
        float sacc = 0.0f;
        for (int k = lane; k < HIDDEN; k += 32)
            sacc += Why[o * HIDDEN + k] * h[k];
        #pragma unroll
        for (int d = 16; d > 0; d >>= 1)
            sacc += __shfl_xor_sync(0xffffffff, sacc, d);
        logits[o] = sacc + by[o];
    }
    if (lane == 0) {
        float mx = logits[0];
        #pragma unroll
        for (int o = 1; o < OUTC; o++) mx = fmaxf(mx, logits[o]);
        float se = 0.0f;
        #pragma unroll
        for (int o = 0; o < OUTC; o++) se += expf(logits[o] - mx);
        float lse = mx + logf(se);
        int sc = scores[gw];
        atomicAdd(out, lse - logits[sc]);
    }
}

// ---------------- launch ----------------
extern "C" void kernel_launch(void* const* d_in, const int* in_sizes, int n_in,
                              void* d_out, int out_size)
{
    const float* Wi   = (const float*)d_in[0];
    const float* bi   = (const float*)d_in[1];
    const float* Wo   = (const float*)d_in[2];
    const float* bo   = (const float*)d_in[3];
    const float* Wu   = (const float*)d_in[4];
    const float* bu   = (const float*)d_in[5];
    const float* U0i  = (const float*)d_in[6];
    const float* U1i  = (const float*)d_in[7];
    const float* bbi  = (const float*)d_in[8];
    const float* U00f = (const float*)d_in[9];
    const float* U01f = (const float*)d_in[10];
    const float* U10f = (const float*)d_in[11];
    const float* U11f = (const float*)d_in[12];
    const float* bbf  = (const float*)d_in[13];
    const float* U0o  = (const float*)d_in[14];
    const float* U1o  = (const float*)d_in[15];
    const float* bbo  = (const float*)d_in[16];
    const float* U0u  = (const float*)d_in[17];
    const float* U1u  = (const float*)d_in[18];
    const float* bbu  = (const float*)d_in[19];
    const float* Why  = (const float*)d_in[20];
    const float* by   = (const float*)d_in[21];
    const float* emb  = (const float*)d_in[22];
    const int*   scores = (const int*)d_in[23];
    const int*   words  = (const int*)d_in[24];

    float* out = (float*)d_out;

    zero_out<<<1, 32>>>(out);
    prep_kernel<<<240, 256>>>(Wi, bi, Wo, bo, Wu, bu,
                              U0i, U1i, bbi,
                              U00f, U01f, U10f, U11f, bbf,
                              U0o, U1o, bbo,
                              U0u, U1u, bbu);

    // leaf: M=4096, GATES=3 — BM=64, BJ=16, ROWS=4 (256 thr), grid (64,10)=640
    {
        dim3 grid(LL / 64, (HIDDEN + 15) / 16);
        fused_level<3, 0, 64, 16, 4><<<grid, 256>>>(0, LL, emb, words);
    }

    // d=11,10: BM=64, BJ=16, ROWS=4 (256 thr) — grids 320 / 160
    for (int d = 11; d >= 10; d--) {
        int s = (1 << d) - 1, M = 1 << d;
        dim3 grid(M / 64, (HIDDEN + 15) / 16);
        fused_level<5, 1, 64, 16, 4><<<grid, 256>>>(s, M, nullptr, nullptr);
    }

    // d=9,8: BM=32, BJ=16, ROWS=4 (128 thr) — grids 160 / 80
    for (int d = 9; d >= 8; d--) {
        int s = (1 << d) - 1, M = 1 << d;
        dim3 grid(M / 32, (HIDDEN + 15) / 16);
        fused_level<5, 1, 32, 16, 4><<<grid, 128>>>(s, M, nullptr, nullptr);
    }

    // d=7..5: BM=16, BJ=16, ROWS=2 (128 thr) — grids 80, 40, 20
    for (int d = 7; d >= 5; d--) {
        int s = (1 << d) - 1, M = 1 << d;
        dim3 grid(M / 16, (HIDDEN + 15) / 16);
        fused_level<5, 1, 16, 16, 2><<<grid, 128>>>(s, M, nullptr, nullptr);
    }

    // d=4..0: warp per (node, j)
    for (int d = 4; d >= 0; d--) {
        int s = (1 << d) - 1, M = 1 << d;
        int warps = M * HIDDEN;
        int blocks = (warps + 7) / 8;
        warp_level<<<blocks, 256>>>(s, M);
    }

    // final loss over all 8191 nodes
    {
        int blocks = (NN + 7) / 8;
        loss_kernel<<<blocks, 256>>>(Why, by, scores, out);
    }
    (void)in_sizes; (void)n_in; (void)out_size;
}

// round 6
// speedup vs baseline: 1.2260x; 1.2260x over previous
#include <cuda_runtime.h>
#include <math.h>

#define HIDDEN 150
#define EMBED 300
#define OUTC 5
#define DEPTH 13
#define NN 8191          // 2^13 - 1
#define LL 4096          // leaves
#define LEAF_START 4095  // 2^12 - 1
#define BK 20            // 300 = 15 * 20

// ---------------- device scratch (no allocs allowed) ----------------
__device__ float g_H[NN * HIDDEN];
__device__ float g_C[NN * HIDDEN];
// gate-interleaved stacked weights: row n = j*GATES + gate, each row 300 wide
__device__ float g_WLi[450 * EMBED];   // leaf: gates {i,o,u}, GATES=3
__device__ float g_WUi[750 * EMBED];   // inner: gates {i,fl,fr,o,u}, GATES=5
__device__ float g_bLi[450];
__device__ float g_bUi[750];

__device__ __forceinline__ float sigmoidf(float x) {
    return 1.0f / (1.0f + expf(-x));
}

// ---------------- weight stacking (gate-interleaved) ----------------
__global__ void prep_kernel(
    const float* __restrict__ Wi, const float* __restrict__ bi,
    const float* __restrict__ Wo, const float* __restrict__ bo,
    const float* __restrict__ Wu, const float* __restrict__ bu,
    const float* __restrict__ U0i, const float* __restrict__ U1i, const float* __restrict__ bbi,
    const float* __restrict__ U00f, const float* __restrict__ U01f,
    const float* __restrict__ U10f, const float* __restrict__ U11f, const float* __restrict__ bbf,
    const float* __restrict__ U0o, const float* __restrict__ U1o, const float* __restrict__ bbo,
    const float* __restrict__ U0u, const float* __restrict__ U1u, const float* __restrict__ bbu)
{
    int t = blockIdx.x * blockDim.x + threadIdx.x;
    int stride = gridDim.x * blockDim.x;

    // leaf weights: n = j*3 + g ; g: 0=i, 1=o, 2=u
    for (int idx = t; idx < 450 * EMBED; idx += stride) {
        int n = idx / EMBED, k = idx % EMBED;
        int j = n / 3, g = n % 3;
        const float* W = (g == 0) ? Wi : (g == 1) ? Wo : Wu;
        g_WLi[idx] = W[j * EMBED + k];
    }
    // inner weights: n = j*5 + g ; g: 0=i, 1=fl, 2=fr, 3=o, 4=u ; cols = [U0 | U1]
    for (int idx = t; idx < 750 * EMBED; idx += stride) {
        int n = idx / EMBED, k = idx % EMBED;
        int j = n / 5, g = n % 5;
        const float* U0; const float* U1;
        switch (g) {
            case 0:  U0 = U0i;  U1 = U1i;  break;
            case 1:  U0 = U00f; U1 = U01f; break;
            case 2:  U0 = U10f; U1 = U11f; break;
            case 3:  U0 = U0o;  U1 = U1o;  break;
            default: U0 = U0u;  U1 = U1u;  break;
        }
        g_WUi[idx] = (k < HIDDEN) ? U0[j * HIDDEN + k] : U1[j * HIDDEN + (k - HIDDEN)];
    }
    if (t < 450) {
        int j = t / 3, g = t % 3;
        g_bLi[t] = (g == 0) ? bi[j] : (g == 1) ? bo[j] : bu[j];
    }
    if (t < 750) {
        int j = t / 5, g = t % 5;
        g_bUi[t] = (g == 0) ? bbi[j] : (g <= 2) ? bbf[j] : (g == 3) ? bbo[j] : bbu[j];
    }
}

// ---------------- fused tiled GEMM + activation ----------------
// thread tile: ROWS rows x 1 j x GATES gates
// block: (BM/ROWS)*BJ threads ; tx = tid % BJ -> j ; ty = tid / BJ -> row group
template<int GATES, int MODE, int BM, int BJ, int ROWS>
__global__ __launch_bounds__((BM / ROWS) * BJ)
void fused_level(int s, int M,
                 const float* __restrict__ emb,
                 const int* __restrict__ words)
{
    constexpr int THREADS = (BM / ROWS) * BJ;
    constexpr int WCOLS = BJ * GATES;
    constexpr int AELEMS = BM * BK;
    constexpr int WELEMS = WCOLS * BK;
    constexpr int NT = EMBED / BK;     // 15 k-tiles

    __shared__ float As[BK][BM];
    __shared__ float Ws[BK][WCOLS];
    __shared__ int   rowOff[BM];

    const float* __restrict__ W     = (MODE == 0) ? g_WLi : g_WUi;
    const float* __restrict__ Abase = (MODE == 0) ? emb : (g_H + (2 * s + 1) * HIDDEN);
    const float* __restrict__ bias  = (MODE == 0) ? g_bLi : g_bUi;

    int bm = blockIdx.x * BM;
    int j0 = blockIdx.y * BJ;
    int n0 = j0 * GATES;
    int tid = threadIdx.x;
    int tx = tid % BJ, ty = tid / BJ;

    for (int e = tid; e < BM; e += THREADS) {
        int m = bm + e;
        int off = -1;
        if (m < M) {
            if (MODE == 0) off = words[LEAF_START + m] * EMBED;
            else           off = m * EMBED;   // children [lh|rh] contiguous
        }
        rowOff[e] = off;
    }
    __syncthreads();

    float acc[ROWS][GATES];
    #pragma unroll
    for (int i = 0; i < ROWS; i++)
        #pragma unroll
        for (int g = 0; g < GATES; g++)
            acc[i][g] = 0.0f;

    #pragma unroll 1
    for (int t = 0; t < NT; t++) {
        int k0 = t * BK;
        #pragma unroll
        for (int e = tid; e < AELEMS; e += THREADS) {
            int ml = e / BK, kk = e % BK;
            int off = rowOff[ml];
            As[kk][ml] = (off >= 0) ? Abase[off + k0 + kk] : 0.0f;
        }
        #pragma unroll
        for (int e = tid; e < WELEMS; e += THREADS) {
            int nl = e / BK, kk = e % BK;
            int n = n0 + nl;
            Ws[kk][nl] = (n < HIDDEN * GATES) ? W[n * EMBED + k0 + kk] : 0.0f;
        }
        __syncthreads();

        #pragma unroll
        for (int kk = 0; kk < BK; kk++) {
            float a[ROWS], w[GATES];
            #pragma unroll
            for (int i = 0; i < ROWS; i++) a[i] = As[kk][ty * ROWS + i];
            #pragma unroll
            for (int g = 0; g < GATES; g++) w[g] = Ws[kk][tx * GATES + g];
            #pragma unroll
            for (int i = 0; i < ROWS; i++)
                #pragma unroll
                for (int g = 0; g < GATES; g++)
                    acc[i][g] += a[i] * w[g];
        }
        __syncthreads();
    }

    int j = j0 + tx;
    if (j >= HIDDEN) return;
    int nb = j * GATES;
    #pragma unroll
    for (int i = 0; i < ROWS; i++) {
        int m = bm + ty * ROWS + i;
        if (m >= M) continue;
        if (MODE == 0) {
            float ig = sigmoidf(acc[i][0] + bias[nb + 0]);
            float og = sigmoidf(acc[i][1] + bias[nb + 1]);
            float uv = tanhf   (acc[i][2] + bias[nb + 2]);
            float c = ig * uv;
            float h = og * tanhf(c);
            int node = LEAF_START + m;
            g_H[node * HIDDEN + j] = h;
            g_C[node * HIDDEN + j] = c;
        } else {
            float ig = sigmoidf(acc[i][0] + bias[nb + 0]);
            float fl = sigmoidf(acc[i][1] + bias[nb + 1]);
            float fr = sigmoidf(acc[i][2] + bias[nb + 2]);
            float og = sigmoidf(acc[i][3] + bias[nb + 3]);
            float uv = tanhf   (acc[i][4] + bias[nb + 4]);
            int node = s + m;
            float lc = g_C[(2 * node + 1) * HIDDEN + j];
            float rc = g_C[(2 * node + 2) * HIDDEN + j];
            float c = ig * uv + fl * lc + fr * rc;
            float h = og * tanhf(c);
            g_H[node * HIDDEN + j] = h;
            g_C[node * HIDDEN + j] = c;
        }
    }
}

// ---------------- warp-per-(node, j) kernel for tiny levels ----------------
__global__ void warp_level(int s, int M)
{
    int wid  = (blockIdx.x * blockDim.x + threadIdx.x) >> 5;
    int lane = threadIdx.x & 31;
    int m = wid / HIDDEN;
    int j = wid % HIDDEN;
    if (m >= M) return;

    const float* __restrict__ A  = g_H + (2 * s + 1 + 2 * m) * HIDDEN;  // 300 contiguous
    const float* __restrict__ Wr = g_WUi + (j * 5) * EMBED;

    float a0 = 0.f, a1 = 0.f, a2 = 0.f, a3 = 0.f, a4 = 0.f;
    #pragma unroll
    for (int kb = 0; kb < EMBED; kb += 32) {
        int k = kb + lane;
        float a = A[k];
        a0 += a * Wr[k];
        a1 += a * Wr[EMBED + k];
        a2 += a * Wr[2 * EMBED + k];
        a3 += a * Wr[3 * EMBED + k];
        a4 += a * Wr[4 * EMBED + k];
    }
    #pragma unroll
    for (int d = 16; d > 0; d >>= 1) {
        a0 += __shfl_xor_sync(0xffffffff, a0, d);
        a1 += __shfl_xor_sync(0xffffffff, a1, d);
        a2 += __shfl_xor_sync(0xffffffff, a2, d);
        a3 += __shfl_xor_sync(0xffffffff, a3, d);
        a4 += __shfl_xor_sync(0xffffffff, a4, d);
    }
    if (lane == 0) {
        int nb = j * 5;
        float ig = sigmoidf(a0 + g_bUi[nb + 0]);
        float fl = sigmoidf(a1 + g_bUi[nb + 1]);
        float fr = sigmoidf(a2 + g_bUi[nb + 2]);
        float og = sigmoidf(a3 + g_bUi[nb + 3]);
        float uv = tanhf   (a4 + g_bUi[nb + 4]);
        int node = s + m;
        float lc = g_C[(2 * node + 1) * HIDDEN + j];
        float rc = g_C[(2 * node + 2) * HIDDEN + j];
        float c = ig * uv + fl * lc + fr * rc;
        float h = og * tanhf(c);
        g_H[node * HIDDEN + j] = h;
        g_C[node * HIDDEN + j] = c;
    }
}

// ---------------- loss ----------------
__global__ void zero_out(float* out)
{
    if (threadIdx.x == 0 && blockIdx.x == 0) out[0] = 0.0f;
}

__global__ void loss_kernel(const float* __restrict__ Why,
                            const float* __restrict__ by,
                            const int*   __restrict__ scores,
                            float* __restrict__ out)
{
    int gw   = (blockIdx.x * blockDim.x + threadIdx.x) >> 5;
    int lane = threadIdx.x & 31;
    if (gw >= NN) return;

    const float* h = g_H + gw * HIDDEN;
    float logits[OUTC];
    #pragma unroll
    for (int o = 0; o < OUTC; o++) {
        float sacc = 0.0f;
        for (int k = lane; k < HIDDEN; k += 32)
            sacc += Why[o * HIDDEN + k] * h[k];
        #pragma unroll
        for (int d = 16; d > 0; d >>= 1)
            sacc += __shfl_xor_sync(0xffffffff, sacc, d);
        logits[o] = sacc + by[o];
    }
    if (lane == 0) {
        float mx = logits[0];
        #pragma unroll
        for (int o = 1; o < OUTC; o++) mx = fmaxf(mx, logits[o]);
        float se = 0.0f;
        #pragma unroll
        for (int o = 0; o < OUTC; o++) se += expf(logits[o] - mx);
        float lse = mx + logf(se);
        int sc = scores[gw];
        atomicAdd(out, lse - logits[sc]);
    }
}

// ---------------- launch ----------------
extern "C" void kernel_launch(void* const* d_in, const int* in_sizes, int n_in,
                              void* d_out, int out_size)
{
    const float* Wi   = (const float*)d_in[0];
    const float* bi   = (const float*)d_in[1];
    const float* Wo   = (const float*)d_in[2];
    const float* bo   = (const float*)d_in[3];
    const float* Wu   = (const float*)d_in[4];
    const float* bu   = (const float*)d_in[5];
    const float* U0i  = (const float*)d_in[6];
    const float* U1i  = (const float*)d_in[7];
    const float* bbi  = (const float*)d_in[8];
    const float* U00f = (const float*)d_in[9];
    const float* U01f = (const float*)d_in[10];
    const float* U10f = (const float*)d_in[11];
    const float* U11f = (const float*)d_in[12];
    const float* bbf  = (const float*)d_in[13];
    const float* U0o  = (const float*)d_in[14];
    const float* U1o  = (const float*)d_in[15];
    const float* bbo  = (const float*)d_in[16];
    const float* U0u  = (const float*)d_in[17];
    const float* U1u  = (const float*)d_in[18];
    const float* bbu  = (const float*)d_in[19];
    const float* Why  = (const float*)d_in[20];
    const float* by   = (const float*)d_in[21];
    const float* emb  = (const float*)d_in[22];
    const int*   scores = (const int*)d_in[23];
    const int*   words  = (const int*)d_in[24];

    float* out = (float*)d_out;

    zero_out<<<1, 32>>>(out);
    prep_kernel<<<240, 256>>>(Wi, bi, Wo, bo, Wu, bu,
                              U0i, U1i, bbi,
                              U00f, U01f, U10f, U11f, bbf,
                              U0o, U1o, bbo,
                              U0u, U1u, bbu);

    // leaf: M=4096, GATES=3 — BM=32, BJ=16, ROWS=4 (128 thr), grid (128,10)=1280
    {
        dim3 grid(LL / 32, (HIDDEN + 15) / 16);
        fused_level<3, 0, 32, 16, 4><<<grid, 128>>>(0, LL, emb, words);
    }

    // d=11..8: BM=32, BJ=16, ROWS=4 (128 thr) — grids 640, 320, 160, 80
    for (int d = 11; d >= 8; d--) {
        int s = (1 << d) - 1, M = 1 << d;
        dim3 grid(M / 32, (HIDDEN + 15) / 16);
        fused_level<5, 1, 32, 16, 4><<<grid, 128>>>(s, M, nullptr, nullptr);
    }

    // d=7..5: BM=16, BJ=16, ROWS=2 (128 thr) — grids 80, 40, 20
    for (int d = 7; d >= 5; d--) {
        int s = (1 << d) - 1, M = 1 << d;
        dim3 grid(M / 16, (HIDDEN + 15) / 16);
        fused_level<5, 1, 16, 16, 2><<<grid, 128>>>(s, M, nullptr, nullptr);
    }

    // d=4..0: warp per (node, j)
    for (int d = 4; d >= 0; d--) {
        int s = (1 << d) - 1, M = 1 << d;
        int warps = M * HIDDEN;
        int blocks = (warps + 7) / 8;
        warp_level<<<blocks, 256>>>(s, M);
    }

    // final loss over all 8191 nodes
    {
        int blocks = (NN + 7) / 8;
        loss_kernel<<<blocks, 256>>>(Why, by, scores, out);
    }
    (void)in_sizes; (void)n_in; (void)out_size;
}

// round 7
// speedup vs baseline: 1.7679x; 1.4419x over previous
#include <cuda_runtime.h>
#include <math.h>

#define HIDDEN 150
#define EMBED 300
#define OUTC 5
#define DEPTH 13
#define NN 8191          // 2^13 - 1
#define LL 4096          // leaves
#define LEAF_START 4095  // 2^12 - 1
#define BK 20            // 300 = 15 * 20

// ---------------- device scratch (no allocs allowed) ----------------
__device__ float g_H[NN * HIDDEN];
__device__ float g_C[NN * HIDDEN];
// transposed, gate-interleaved weights: WT[k][n], n = j*GATES + gate
__device__ float g_WLt[EMBED * 450];   // leaf: gates {i,o,u}
__device__ float g_WUt[EMBED * 750];   // inner: gates {i,fl,fr,o,u}
// row-major copy for warp_level tail
__device__ float g_WUi[750 * EMBED];
__device__ float g_bLi[450];
__device__ float g_bUi[750];

__device__ __forceinline__ float sigmoidf(float x) {
    return 1.0f / (1.0f + expf(-x));
}

// ---------------- weight stacking ----------------
__global__ void prep_kernel(
    const float* __restrict__ Wi, const float* __restrict__ bi,
    const float* __restrict__ Wo, const float* __restrict__ bo,
    const float* __restrict__ Wu, const float* __restrict__ bu,
    const float* __restrict__ U0i, const float* __restrict__ U1i, const float* __restrict__ bbi,
    const float* __restrict__ U00f, const float* __restrict__ U01f,
    const float* __restrict__ U10f, const float* __restrict__ U11f, const float* __restrict__ bbf,
    const float* __restrict__ U0o, const float* __restrict__ U1o, const float* __restrict__ bbo,
    const float* __restrict__ U0u, const float* __restrict__ U1u, const float* __restrict__ bbu)
{
    int t = blockIdx.x * blockDim.x + threadIdx.x;
    int stride = gridDim.x * blockDim.x;

    // leaf transposed: WLt[k*450 + n], n = j*3 + g ; g: 0=i,1=o,2=u
    for (int idx = t; idx < EMBED * 450; idx += stride) {
        int k = idx / 450, n = idx % 450;
        int j = n / 3, g = n % 3;
        const float* W = (g == 0) ? Wi : (g == 1) ? Wo : Wu;
        g_WLt[idx] = W[j * EMBED + k];
    }
    // inner: n = j*5 + g ; g: 0=i,1=fl,2=fr,3=o,4=u ; k<150 -> U0, else U1
    for (int idx = t; idx < EMBED * 750; idx += stride) {
        int k = idx / 750, n = idx % 750;
        int j = n / 5, g = n % 5;
        const float* U0; const float* U1;
        switch (g) {
            case 0:  U0 = U0i;  U1 = U1i;  break;
            case 1:  U0 = U00f; U1 = U01f; break;
            case 2:  U0 = U10f; U1 = U11f; break;
            case 3:  U0 = U0o;  U1 = U1o;  break;
            default: U0 = U0u;  U1 = U1u;  break;
        }
        float v = (k < HIDDEN) ? U0[j * HIDDEN + k] : U1[j * HIDDEN + (k - HIDDEN)];
        g_WUt[idx] = v;
        g_WUi[n * EMBED + k] = v;   // row-major copy for warp_level
    }
    if (t < 450) {
        int j = t / 3, g = t % 3;
        g_bLi[t] = (g == 0) ? bi[j] : (g == 1) ? bo[j] : bu[j];
    }
    if (t < 750) {
        int j = t / 5, g = t % 5;
        g_bUi[t] = (g == 0) ? bbi[j] : (g <= 2) ? bbf[j] : (g == 3) ? bbo[j] : bbu[j];
    }
}

// ---------------- fused tiled GEMM + activation (double-buffered) ----------------
// thread tile: ROWS rows x 1 j x GATES gates
template<int GATES, int MODE, int BM, int BJ, int ROWS>
__global__ __launch_bounds__((BM / ROWS) * BJ)
void fused_level(int s, int M,
                 const float* __restrict__ emb,
                 const int* __restrict__ words)
{
    constexpr int THREADS = (BM / ROWS) * BJ;
    constexpr int WCOLS = BJ * GATES;
    constexpr int NTOT = HIDDEN * GATES;
    constexpr int AELEMS = BM * BK;
    constexpr int WELEMS = WCOLS * BK;
    constexpr int LA = (AELEMS + THREADS - 1) / THREADS;
    constexpr int LW = (WELEMS + THREADS - 1) / THREADS;
    constexpr bool AEXACT = (AELEMS % THREADS) == 0;
    constexpr bool WEXACT = (WELEMS % THREADS) == 0;
    constexpr int NT = EMBED / BK;     // 15 k-tiles

    __shared__ float As[2][BK][BM];
    __shared__ float Ws[2][BK][WCOLS];
    __shared__ int   rowOff[BM];

    const float* __restrict__ WT    = (MODE == 0) ? g_WLt : g_WUt;
    const float* __restrict__ Abase = (MODE == 0) ? emb : (g_H + (2 * s + 1) * HIDDEN);
    const float* __restrict__ bias  = (MODE == 0) ? g_bLi : g_bUi;

    int bm = blockIdx.x * BM;
    int j0 = blockIdx.y * BJ;
    int n0 = j0 * GATES;
    int tid = threadIdx.x;
    int tx = tid % BJ, ty = tid / BJ;

    for (int e = tid; e < BM; e += THREADS) {
        int m = bm + e;
        int off = -1;
        if (m < M) {
            if (MODE == 0) off = words[LEAF_START + m] * EMBED;
            else           off = m * EMBED;   // children [lh|rh] contiguous
        }
        rowOff[e] = off;
    }
    __syncthreads();

    float ra[LA], rw[LW];

    auto fetch = [&](int k0) {
        #pragma unroll
        for (int l = 0; l < LA; l++) {
            int e = tid + l * THREADS;
            if (AEXACT || e < AELEMS) {
                int ml = e / BK, kk = e % BK;
                int off = rowOff[ml];
                ra[l] = (off >= 0) ? Abase[off + k0 + kk] : 0.0f;
            }
        }
        #pragma unroll
        for (int l = 0; l < LW; l++) {
            int e = tid + l * THREADS;
            if (WEXACT || e < WELEMS) {
                int kk = e / WCOLS, nl = e % WCOLS;
                int n = n0 + nl;
                rw[l] = (n < NTOT) ? WT[(k0 + kk) * NTOT + n] : 0.0f;
            }
        }
    };
    auto stage = [&](int b) {
        #pragma unroll
        for (int l = 0; l < LA; l++) {
            int e = tid + l * THREADS;
            if (AEXACT || e < AELEMS) {
                int ml = e / BK, kk = e % BK;
                As[b][kk][ml] = ra[l];
            }
        }
        #pragma unroll
        for (int l = 0; l < LW; l++) {
            int e = tid + l * THREADS;
            if (WEXACT || e < WELEMS) {
                int kk = e / WCOLS, nl = e % WCOLS;
                Ws[b][kk][nl] = rw[l];
            }
        }
    };

    float acc[ROWS][GATES];
    #pragma unroll
    for (int i = 0; i < ROWS; i++)
        #pragma unroll
        for (int g = 0; g < GATES; g++)
            acc[i][g] = 0.0f;

    fetch(0);
    stage(0);
    __syncthreads();

    #pragma unroll 1
    for (int t = 0; t < NT; t++) {
        int b = t & 1;
        if (t + 1 < NT) fetch((t + 1) * BK);

        #pragma unroll
        for (int kk = 0; kk < BK; kk++) {
            float a[ROWS], w[GATES];
            if (ROWS == 4) {
                float4 av = *reinterpret_cast<const float4*>(&As[b][kk][ty * 4]);
                a[0] = av.x; a[1] = av.y; a[2] = av.z; a[3] = av.w;
            } else if (ROWS == 2) {
                float2 av = *reinterpret_cast<const float2*>(&As[b][kk][ty * 2]);
                a[0] = av.x; a[1] = av.y;
            } else {
                #pragma unroll
                for (int i = 0; i < ROWS; i++) a[i] = As[b][kk][ty * ROWS + i];
            }
            #pragma unroll
            for (int g = 0; g < GATES; g++) w[g] = Ws[b][kk][tx * GATES + g];
            #pragma unroll
            for (int i = 0; i < ROWS; i++)
                #pragma unroll
                for (int g = 0; g < GATES; g++)
                    acc[i][g] += a[i] * w[g];
        }
        if (t + 1 < NT) stage(b ^ 1);
        __syncthreads();
    }

    int j = j0 + tx;
    if (j >= HIDDEN) return;
    int nb = j * GATES;
    #pragma unroll
    for (int i = 0; i < ROWS; i++) {
        int m = bm + ty * ROWS + i;
        if (m >= M) continue;
        if (MODE == 0) {
            float ig = sigmoidf(acc[i][0] + bias[nb + 0]);
            float og = sigmoidf(acc[i][1] + bias[nb + 1]);
            float uv = tanhf   (acc[i][2] + bias[nb + 2]);
            float c = ig * uv;
            float h = og * tanhf(c);
            int node = LEAF_START + m;
            g_H[node * HIDDEN + j] = h;
            g_C[node * HIDDEN + j] = c;
        } else {
            float ig = sigmoidf(acc[i][0] + bias[nb + 0]);
            float fl = sigmoidf(acc[i][1] + bias[nb + 1]);
            float fr = sigmoidf(acc[i][2] + bias[nb + 2]);
            float og = sigmoidf(acc[i][3] + bias[nb + 3]);
            float uv = tanhf   (acc[i][4] + bias[nb + 4]);
            int node = s + m;
            float lc = g_C[(2 * node + 1) * HIDDEN + j];
            float rc = g_C[(2 * node + 2) * HIDDEN + j];
            float c = ig * uv + fl * lc + fr * rc;
            float h = og * tanhf(c);
            g_H[node * HIDDEN + j] = h;
            g_C[node * HIDDEN + j] = c;
        }
    }
}

// ---------------- warp-per-(node, j) kernel for tiny levels ----------------
__global__ void warp_level(int s, int M)
{
    int wid  = (blockIdx.x * blockDim.x + threadIdx.x) >> 5;
    int lane = threadIdx.x & 31;
    int m = wid / HIDDEN;
    int j = wid % HIDDEN;
    if (m >= M) return;

    const float* __restrict__ A  = g_H + (2 * s + 1 + 2 * m) * HIDDEN;  // 300 contiguous
    const float* __restrict__ Wr = g_WUi + (j * 5) * EMBED;

    float a0 = 0.f, a1 = 0.f, a2 = 0.f, a3 = 0.f, a4 = 0.f;
    #pragma unroll
    for (int kb = 0; kb < EMBED; kb += 32) {
        int k = kb + lane;
        float a = A[k];
        a0 += a * Wr[k];
        a1 += a * Wr[EMBED + k];
        a2 += a * Wr[2 * EMBED + k];
        a3 += a * Wr[3 * EMBED + k];
        a4 += a * Wr[4 * EMBED + k];
    }
    #pragma unroll
    for (int d = 16; d > 0; d >>= 1) {
        a0 += __shfl_xor_sync(0xffffffff, a0, d);
        a1 += __shfl_xor_sync(0xffffffff, a1, d);
        a2 += __shfl_xor_sync(0xffffffff, a2, d);
        a3 += __shfl_xor_sync(0xffffffff, a3, d);
        a4 += __shfl_xor_sync(0xffffffff, a4, d);
    }
    if (lane == 0) {
        int nb = j * 5;
        float ig = sigmoidf(a0 + g_bUi[nb + 0]);
        float fl = sigmoidf(a1 + g_bUi[nb + 1]);
        float fr = sigmoidf(a2 + g_bUi[nb + 2]);
        float og = sigmoidf(a3 + g_bUi[nb + 3]);
        float uv = tanhf   (a4 + g_bUi[nb + 4]);
        int node = s + m;
        float lc = g_C[(2 * node + 1) * HIDDEN + j];
        float rc = g_C[(2 * node + 2) * HIDDEN + j];
        float c = ig * uv + fl * lc + fr * rc;
        float h = og * tanhf(c);
        g_H[node * HIDDEN + j] = h;
        g_C[node * HIDDEN + j] = c;
    }
}

// ---------------- loss ----------------
__global__ void zero_out(float* out)
{
    if (threadIdx.x == 0 && blockIdx.x == 0) out[0] = 0.0f;
}

__global__ void loss_kernel(const float* __restrict__ Why,
                            const float* __restrict__ by,
                            const int*   __restrict__ scores,
                            float* __restrict__ out)
{
    int gw   = (blockIdx.x * blockDim.x + threadIdx.x) >> 5;
    int lane = threadIdx.x & 31;
    if (gw >= NN) return;

    const float* h = g_H + gw * HIDDEN;
    float logits[OUTC];
    #pragma unroll
    for (int o = 0; o < OUTC; o++) {
        float sacc = 0.0f;
        for (int k = lane; k < HIDDEN; k += 32)
            sacc += Why[o * HIDDEN + k] * h[k];
        #pragma unroll
        for (int d = 16; d > 0; d >>= 1)
            sacc += __shfl_xor_sync(0xffffffff, sacc, d);
        logits[o] = sacc + by[o];
    }
    if (lane == 0) {
        float mx = logits[0];
        #pragma unroll
        for (int o = 1; o < OUTC; o++) mx = fmaxf(mx, logits[o]);
        float se = 0.0f;
        #pragma unroll
        for (int o = 0; o < OUTC; o++) se += expf(logits[o] - mx);
        float lse = mx + logf(se);
        int sc = scores[gw];
        atomicAdd(out, lse - logits[sc]);
    }
}

// ---------------- launch ----------------
extern "C" void kernel_launch(void* const* d_in, const int* in_sizes, int n_in,
                              void* d_out, int out_size)
{
    const float* Wi   = (const float*)d_in[0];
    const float* bi   = (const float*)d_in[1];
    const float* Wo   = (const float*)d_in[2];
    const float* bo   = (const float*)d_in[3];
    const float* Wu   = (const float*)d_in[4];
    const float* bu   = (const float*)d_in[5];
    const float* U0i  = (const float*)d_in[6];
    const float* U1i  = (const float*)d_in[7];
    const float* bbi  = (const float*)d_in[8];
    const float* U00f = (const float*)d_in[9];
    const float* U01f = (const float*)d_in[10];
    const float* U10f = (const float*)d_in[11];
    const float* U11f = (const float*)d_in[12];
    const float* bbf  = (const float*)d_in[13];
    const float* U0o  = (const float*)d_in[14];
    const float* U1o  = (const float*)d_in[15];
    const float* bbo  = (const float*)d_in[16];
    const float* U0u  = (const float*)d_in[17];
    const float* U1u  = (const float*)d_in[18];
    const float* bbu  = (const float*)d_in[19];
    const float* Why  = (const float*)d_in[20];
    const float* by   = (const float*)d_in[21];
    const float* emb  = (const float*)d_in[22];
    const int*   scores = (const int*)d_in[23];
    const int*   words  = (const int*)d_in[24];

    float* out = (float*)d_out;

    zero_out<<<1, 32>>>(out);
    prep_kernel<<<240, 256>>>(Wi, bi, Wo, bo, Wu, bu,
                              U0i, U1i, bbi,
                              U00f, U01f, U10f, U11f, bbf,
                              U0o, U1o, bbo,
                              U0u, U1u, bbu);

    // leaf: M=4096, GATES=3 — BM=64, BJ=16, ROWS=4 (256 thr), grid (64,10)
    {
        dim3 grid(LL / 64, (HIDDEN + 15) / 16);
        fused_level<3, 0, 64, 16, 4><<<grid, 256>>>(0, LL, emb, words);
    }

    // d=11,10: BM=64, BJ=16, ROWS=4 (256 thr) — grids 320 / 160
    for (int d = 11; d >= 10; d--) {
        int s = (1 << d) - 1, M = 1 << d;
        dim3 grid(M / 64, (HIDDEN + 15) / 16);
        fused_level<5, 1, 64, 16, 4><<<grid, 256>>>(s, M, nullptr, nullptr);
    }

    // d=9,8: BM=32, BJ=16, ROWS=4 (128 thr) — grids 160 / 80
    for (int d = 9; d >= 8; d--) {
        int s = (1 << d) - 1, M = 1 << d;
        dim3 grid(M / 32, (HIDDEN + 15) / 16);
        fused_level<5, 1, 32, 16, 4><<<grid, 128>>>(s, M, nullptr, nullptr);
    }

    // d=7,6: BM=16, BJ=16, ROWS=2 (128 thr) — grids 80 / 40
    for (int d = 7; d >= 6; d--) {
        int s = (1 << d) - 1, M = 1 << d;
        dim3 grid(M / 16, (HIDDEN + 15) / 16);
        fused_level<5, 1, 16, 16, 2><<<grid, 128>>>(s, M, nullptr, nullptr);
    }

    // d=5..0: warp per (node, j)
    for (int d = 5; d >= 0; d--) {
        int s = (1 << d) - 1, M = 1 << d;
        int warps = M * HIDDEN;
        int blocks = (warps + 7) / 8;
        warp_level<<<blocks, 256>>>(s, M);
    }

    // final loss over all 8191 nodes
    {
        int blocks = (NN + 7) / 8;
        loss_kernel<<<blocks, 256>>>(Why, by, scores, out);
    }
    (void)in_sizes; (void)n_in; (void)out_size;
}

// round 9
// speedup vs baseline: 1.9307x; 1.0921x over previous
#include <cuda_runtime.h>
#include <math.h>

#define HIDDEN 150
#define EMBED 300
#define OUTC 5
#define DEPTH 13
#define NN 8191          // 2^13 - 1
#define LL 4096          // leaves
#define LEAF_START 4095  // 2^12 - 1
#define BK 20            // 300 = 15 * 20
#define NPAD_L 480       // padded leaf columns (>= 160*3)
#define NPAD_U 800       // padded inner columns (>= 160*5)

// ---------------- device scratch (no allocs allowed) ----------------
__device__ float g_H[NN * HIDDEN];
__device__ float g_C[NN * HIDDEN];
// transposed, gate-interleaved, column-PADDED weights: WT[k][n], n = j*GATES + gate
__device__ float g_WLt[EMBED * NPAD_L];
__device__ float g_WUt[EMBED * NPAD_U];
// row-major copy for warp_level tail
__device__ float g_WUi[750 * EMBED];
__device__ float g_bLi[480];
__device__ float g_bUi[800];

__device__ __forceinline__ float sigmoidf(float x) {
    return 1.0f / (1.0f + expf(-x));
}

// ---------------- weight stacking ----------------
__global__ void prep_kernel(
    const float* __restrict__ Wi, const float* __restrict__ bi,
    const float* __restrict__ Wo, const float* __restrict__ bo,
    const float* __restrict__ Wu, const float* __restrict__ bu,
    const float* __restrict__ U0i, const float* __restrict__ U1i, const float* __restrict__ bbi,
    const float* __restrict__ U00f, const float* __restrict__ U01f,
    const float* __restrict__ U10f, const float* __restrict__ U11f, const float* __restrict__ bbf,
    const float* __restrict__ U0o, const float* __restrict__ U1o, const float* __restrict__ bbo,
    const float* __restrict__ U0u, const float* __restrict__ U1u, const float* __restrict__ bbu)
{
    int t = blockIdx.x * blockDim.x + threadIdx.x;
    int stride = gridDim.x * blockDim.x;

    // leaf transposed: WLt[k*NPAD_L + n], n = j*3 + g ; g: 0=i,1=o,2=u
    for (int idx = t; idx < EMBED * NPAD_L; idx += stride) {
        int k = idx / NPAD_L, n = idx % NPAD_L;
        float v = 0.0f;
        if (n < 450) {
            int j = n / 3, g = n % 3;
            const float* W = (g == 0) ? Wi : (g == 1) ? Wo : Wu;
            v = W[j * EMBED + k];
        }
        g_WLt[idx] = v;
    }
    // inner: n = j*5 + g ; g: 0=i,1=fl,2=fr,3=o,4=u ; k<150 -> U0, else U1
    for (int idx = t; idx < EMBED * NPAD_U; idx += stride) {
        int k = idx / NPAD_U, n = idx % NPAD_U;
        float v = 0.0f;
        if (n < 750) {
            int j = n / 5, g = n % 5;
            const float* U0; const float* U1;
            switch (g) {
                case 0:  U0 = U0i;  U1 = U1i;  break;
                case 1:  U0 = U00f; U1 = U01f; break;
                case 2:  U0 = U10f; U1 = U11f; break;
                case 3:  U0 = U0o;  U1 = U1o;  break;
                default: U0 = U0u;  U1 = U1u;  break;
            }
            v = (k < HIDDEN) ? U0[j * HIDDEN + k] : U1[j * HIDDEN + (k - HIDDEN)];
            g_WUi[n * EMBED + k] = v;   // row-major copy for warp_level
        }
        g_WUt[idx] = v;
    }
    if (t < 480) {
        float v = 0.0f;
        if (t < 450) {
            int j = t / 3, g = t % 3;
            v = (g == 0) ? bi[j] : (g == 1) ? bo[j] : bu[j];
        }
        g_bLi[t] = v;
    }
    if (t < 800) {
        float v = 0.0f;
        if (t < 750) {
            int j = t / 5, g = t % 5;
            v = (g == 0) ? bbi[j] : (g <= 2) ? bbf[j] : (g == 3) ? bbo[j] : bbu[j];
        }
        g_bUi[t] = v;
    }
}

// ---------------- fused tiled GEMM + activation (double-buffered, no div/mod in loop) --------
// thread tile: ROWS rows x 1 j x GATES gates. Requires M % BM == 0.
template<int GATES, int MODE, int BM, int BJ, int ROWS>
__global__ __launch_bounds__((BM / ROWS) * BJ)
void fused_level(int s, int M,
                 const float* __restrict__ emb,
                 const int* __restrict__ words)
{
    constexpr int THREADS = (BM / ROWS) * BJ;
    constexpr int WCOLS = BJ * GATES;
    constexpr int NTOTP = (MODE == 0) ? NPAD_L : NPAD_U;
    constexpr int AELEMS = BM * BK;
    constexpr int WELEMS = WCOLS * BK;
    constexpr int LA = (AELEMS + THREADS - 1) / THREADS;
    constexpr int LW = (WELEMS + THREADS - 1) / THREADS;
    static_assert(LA * THREADS < 2 * AELEMS, "A wrap-around requires <2x overshoot");
    static_assert(LW * THREADS < 2 * WELEMS, "W wrap-around requires <2x overshoot");
    constexpr int NT = EMBED / BK;     // 15 k-tiles

    __shared__ float As[2][BK][BM];
    __shared__ float Ws[2][BK][WCOLS];
    __shared__ int   rowOff[BM];

    const float* __restrict__ WT    = (MODE == 0) ? g_WLt : g_WUt;
    const float* __restrict__ Abase = (MODE == 0) ? emb : (g_H + (2 * s + 1) * HIDDEN);
    const float* __restrict__ bias  = (MODE == 0) ? g_bLi : g_bUi;

    int bm = blockIdx.x * BM;
    int j0 = blockIdx.y * BJ;
    int n0 = j0 * GATES;
    int tid = threadIdx.x;
    int tx = tid % BJ, ty = tid / BJ;

    for (int e = tid; e < BM; e += THREADS) {
        int m = bm + e;
        rowOff[e] = (MODE == 0) ? words[LEAF_START + m] * EMBED : m * EMBED;
    }
    __syncthreads();

    // ---- precomputed index tables (all div/mod done once) ----
    // wrap-around: overhang threads re-load/store element (e - ELEMS):
    // identical value to the thread that owns it -> benign duplicate store.
    int aGOff[LA], aSOff[LA];
    #pragma unroll
    for (int l = 0; l < LA; l++) {
        int e = tid + l * THREADS;
        if (e >= AELEMS) e -= AELEMS;
        int ml = e / BK, kk = e % BK;
        aGOff[l] = rowOff[ml] + kk;      // + k0 per tile
        aSOff[l] = kk * BM + ml;         // element offset within As buffer
    }
    int wGOff[LW], wSOff[LW];
    #pragma unroll
    for (int l = 0; l < LW; l++) {
        int e = tid + l * THREADS;
        if (e >= WELEMS) e -= WELEMS;
        int kk = e / WCOLS, nl = e % WCOLS;
        wGOff[l] = kk * NTOTP + n0 + nl; // + k0*NTOTP per tile
        wSOff[l] = kk * WCOLS + nl;
    }

    float* AsF = &As[0][0][0];
    float* WsF = &Ws[0][0][0];
    constexpr int ABUF = BK * BM;
    constexpr int WBUF = BK * WCOLS;

    float ra[LA], rw[LW];
    auto fetch = [&](int k0) {
        #pragma unroll
        for (int l = 0; l < LA; l++) ra[l] = Abase[aGOff[l] + k0];
        int wk = k0 * NTOTP;
        #pragma unroll
        for (int l = 0; l < LW; l++) rw[l] = WT[wGOff[l] + wk];
    };
    auto stage = [&](int boff_a, int boff_w) {
        #pragma unroll
        for (int l = 0; l < LA; l++) AsF[boff_a + aSOff[l]] = ra[l];
        #pragma unroll
        for (int l = 0; l < LW; l++) WsF[boff_w + wSOff[l]] = rw[l];
    };

    float acc[ROWS][GATES];
    #pragma unroll
    for (int i = 0; i < ROWS; i++)
        #pragma unroll
        for (int g = 0; g < GATES; g++)
            acc[i][g] = 0.0f;

    fetch(0);
    stage(0, 0);
    __syncthreads();

    #pragma unroll 1
    for (int t = 0; t < NT; t++) {
        int b = t & 1;
        if (t + 1 < NT) fetch((t + 1) * BK);

        const float* Ab = AsF + b * ABUF;
        const float* Wb = WsF + b * WBUF;
        #pragma unroll
        for (int kk = 0; kk < BK; kk++) {
            float a[ROWS], w[GATES];
            if (ROWS == 4) {
                float4 av = *reinterpret_cast<const float4*>(Ab + kk * BM + ty * 4);
                a[0] = av.x; a[1] = av.y; a[2] = av.z; a[3] = av.w;
            } else if (ROWS == 2) {
                float2 av = *reinterpret_cast<const float2*>(Ab + kk * BM + ty * 2);
                a[0] = av.x; a[1] = av.y;
            } else {
                #pragma unroll
                for (int i = 0; i < ROWS; i++) a[i] = Ab[kk * BM + ty * ROWS + i];
            }
            #pragma unroll
            for (int g = 0; g < GATES; g++) w[g] = Wb[kk * WCOLS + tx * GATES + g];
            #pragma unroll
            for (int i = 0; i < ROWS; i++)
                #pragma unroll
                for (int g = 0; g < GATES; g++)
                    acc[i][g] += a[i] * w[g];
        }
        if (t + 1 < NT) stage((b ^ 1) * ABUF, (b ^ 1) * WBUF);
        __syncthreads();
    }

    int j = j0 + tx;
    if (j >= HIDDEN) return;
    int nb = j * GATES;
    #pragma unroll
    for (int i = 0; i < ROWS; i++) {
        int m = bm + ty * ROWS + i;
        if (MODE == 0) {
            float ig = sigmoidf(acc[i][0] + bias[nb + 0]);
            float og = sigmoidf(acc[i][1] + bias[nb + 1]);
            float uv = tanhf   (acc[i][2] + bias[nb + 2]);
            float c = ig * uv;
            float h = og * tanhf(c);
            int node = LEAF_START + m;
            g_H[node * HIDDEN + j] = h;
            g_C[node * HIDDEN + j] = c;
        } else {
            float ig = sigmoidf(acc[i][0] + bias[nb + 0]);
            float fl = sigmoidf(acc[i][1] + bias[nb + 1]);
            float fr = sigmoidf(acc[i][2] + bias[nb + 2]);
            float og = sigmoidf(acc[i][3] + bias[nb + 3]);
            float uv = tanhf   (acc[i][4] + bias[nb + 4]);
            int node = s + m;
            float lc = g_C[(2 * node + 1) * HIDDEN + j];
            float rc = g_C[(2 * node + 2) * HIDDEN + j];
            float c = ig * uv + fl * lc + fr * rc;
            float h = og * tanhf(c);
            g_H[node * HIDDEN + j] = h;
            g_C[node * HIDDEN + j] = c;
        }
    }
}

// ---------------- warp-per-(node, j) kernel for tiny levels ----------------
__global__ void warp_level(int s, int M)
{
    int wid  = (blockIdx.x * blockDim.x + threadIdx.x) >> 5;
    int lane = threadIdx.x & 31;
    int m = wid / HIDDEN;
    int j = wid % HIDDEN;
    if (m >= M) return;

    const float* __restrict__ A  = g_H + (2 * s + 1 + 2 * m) * HIDDEN;  // 300 contiguous
    const float* __restrict__ Wr = g_WUi + (j * 5) * EMBED;

    float a0 = 0.f, a1 = 0.f, a2 = 0.f, a3 = 0.f, a4 = 0.f;
    #pragma unroll
    for (int kb = 0; kb < EMBED; kb += 32) {
        int k = kb + lane;
        float a = A[k];
        a0 += a * Wr[k];
        a1 += a * Wr[EMBED + k];
        a2 += a * Wr[2 * EMBED + k];
        a3 += a * Wr[3 * EMBED + k];
        a4 += a * Wr[4 * EMBED + k];
    }
    #pragma unroll
    for (int d = 16; d > 0; d >>= 1) {
        a0 += __shfl_xor_sync(0xffffffff, a0, d);
        a1 += __shfl_xor_sync(0xffffffff, a1, d);
        a2 += __shfl_xor_sync(0xffffffff, a2, d);
        a3 += __shfl_xor_sync(0xffffffff, a3, d);
        a4 += __shfl_xor_sync(0xffffffff, a4, d);
    }
    if (lane == 0) {
        int nb = j * 5;
        float ig = sigmoidf(a0 + g_bUi[nb + 0]);
        float fl = sigmoidf(a1 + g_bUi[nb + 1]);
        float fr = sigmoidf(a2 + g_bUi[nb + 2]);
        float og = sigmoidf(a3 + g_bUi[nb + 3]);
        float uv = tanhf   (a4 + g_bUi[nb + 4]);
        int node = s + m;
        float lc = g_C[(2 * node + 1) * HIDDEN + j];
        float rc = g_C[(2 * node + 2) * HIDDEN + j];
        float c = ig * uv + fl * lc + fr * rc;
        float h = og * tanhf(c);
        g_H[node * HIDDEN + j] = h;
        g_C[node * HIDDEN + j] = c;
    }
}

// ---------------- loss ----------------
__global__ void zero_out(float* out)
{
    if (threadIdx.x == 0 && blockIdx.x == 0) out[0] = 0.0f;
}

__global__ void loss_kernel(const float* __restrict__ Why,
                            const float* __restrict__ by,
                            const int*   __restrict__ scores,
                            float* __restrict__ out)
{
    int gw   = (blockIdx.x * blockDim.x + threadIdx.x) >> 5;
    int lane = threadIdx.x & 31;
    if (gw >= NN) return;

    const float* h = g_H + gw * HIDDEN;
    float logits[OUTC];
    #pragma unroll
    for (int o = 0; o < OUTC; o++) {
        float sacc = 0.0f;
        for (int k = lane; k < HIDDEN; k += 32)
            sacc += Why[o * HIDDEN + k] * h[k];
        #pragma unroll
        for (int d = 16; d > 0; d >>= 1)
            sacc += __shfl_xor_sync(0xffffffff, sacc, d);
        logits[o] = sacc + by[o];
    }
    if (lane == 0) {
        float mx = logits[0];
        #pragma unroll
        for (int o = 1; o < OUTC; o++) mx = fmaxf(mx, logits[o]);
        float se = 0.0f;
        #pragma unroll
        for (int o = 0; o < OUTC; o++) se += expf(logits[o] - mx);
        float lse = mx + logf(se);
        int sc = scores[gw];
        atomicAdd(out, lse - logits[sc]);
    }
}

// ---------------- launch ----------------
extern "C" void kernel_launch(void* const* d_in, const int* in_sizes, int n_in,
                              void* d_out, int out_size)
{
    const float* Wi   = (const float*)d_in[0];
    const float* bi   = (const float*)d_in[1];
    const float* Wo   = (const float*)d_in[2];
    const float* bo   = (const float*)d_in[3];
    const float* Wu   = (const float*)d_in[4];
    const float* bu   = (const float*)d_in[5];
    const float* U0i  = (const float*)d_in[6];
    const float* U1i  = (const float*)d_in[7];
    const float* bbi  = (const float*)d_in[8];
    const float* U00f = (const float*)d_in[9];
    const float* U01f = (const float*)d_in[10];
    const float* U10f = (const float*)d_in[11];
    const float* U11f = (const float*)d_in[12];
    const float* bbf  = (const float*)d_in[13];
    const float* U0o  = (const float*)d_in[14];
    const float* U1o  = (const float*)d_in[15];
    const float* bbo  = (const float*)d_in[16];
    const float* U0u  = (const float*)d_in[17];
    const float* U1u  = (const float*)d_in[18];
    const float* bbu  = (const float*)d_in[19];
    const float* Why  = (const float*)d_in[20];
    const float* by   = (const float*)d_in[21];
    const float* emb  = (const float*)d_in[22];
    const int*   scores = (const int*)d_in[23];
    const int*   words  = (const int*)d_in[24];

    float* out = (float*)d_out;

    zero_out<<<1, 32>>>(out);
    prep_kernel<<<240, 256>>>(Wi, bi, Wo, bo, Wu, bu,
                              U0i, U1i, bbi,
                              U00f, U01f, U10f, U11f, bbf,
                              U0o, U1o, bbo,
                              U0u, U1u, bbu);

    // leaf: M=4096, GATES=3 — BM=64, BJ=16, ROWS=4 (256 thr), grid (64,10)
    {
        dim3 grid(LL / 64, (HIDDEN + 15) / 16);
        fused_level<3, 0, 64, 16, 4><<<grid, 256>>>(0, LL, emb, words);
    }

    // d=11,10: BM=64, BJ=16, ROWS=4 (256 thr) — grids 320 / 160
    for (int d = 11; d >= 10; d--) {
        int s = (1 << d) - 1, M = 1 << d;
        dim3 grid(M / 64, (HIDDEN + 15) / 16);
        fused_level<5, 1, 64, 16, 4><<<grid, 256>>>(s, M, nullptr, nullptr);
    }

    // d=9,8: BM=32, BJ=16, ROWS=4 (128 thr) — grids 160 / 80
    for (int d = 9; d >= 8; d--) {
        int s = (1 << d) - 1, M = 1 << d;
        dim3 grid(M / 32, (HIDDEN + 15) / 16);
        fused_level<5, 1, 32, 16, 4><<<grid, 128>>>(s, M, nullptr, nullptr);
    }

    // d=7,6: BM=16, BJ=16, ROWS=2 (128 thr) — grids 80 / 40
    for (int d = 7; d >= 6; d--) {
        int s = (1 << d) - 1, M = 1 << d;
        dim3 grid(M / 16, (HIDDEN + 15) / 16);
        fused_level<5, 1, 16, 16, 2><<<grid, 128>>>(s, M, nullptr, nullptr);
    }

    // d=5..0: warp per (node, j)
    for (int d = 5; d >= 0; d--) {
        int s = (1 << d) - 1, M = 1 << d;
        int warps = M * HIDDEN;
        int blocks = (warps + 7) / 8;
        warp_level<<<blocks, 256>>>(s, M);
    }

    // final loss over all 8191 nodes
    {
        int blocks = (NN + 7) / 8;
        loss_kernel<<<blocks, 256>>>(Why, by, scores, out);
    }
    (void)in_sizes; (void)n_in; (void)out_size;
}

// round 10
// speedup vs baseline: 2.0683x; 1.0713x over previous
#include <cuda_runtime.h>
#include <math.h>

#define HIDDEN 150
#define EMBED 300
#define OUTC 5
#define DEPTH 13
#define NN 8191          // 2^13 - 1
#define LL 4096          // leaves
#define LEAF_START 4095  // 2^12 - 1
#define BK 20            // 300 = 15 * 20
#define NPAD_L 480       // padded leaf columns (>= 160*3)
#define NPAD_U 800       // padded inner columns (>= 160*5)

// ---------------- device scratch (no allocs allowed) ----------------
__device__ float g_H[NN * HIDDEN];
__device__ float g_C[NN * HIDDEN];
// transposed, gate-interleaved, column-PADDED weights: WT[k][n], n = j*GATES + gate
__device__ float g_WLt[EMBED * NPAD_L];
__device__ float g_WUt[EMBED * NPAD_U];
// row-major copy for warp_level tail
__device__ float g_WUi[750 * EMBED];
__device__ float g_bLi[480];
__device__ float g_bUi[800];

__device__ __forceinline__ float sigmoidf(float x) {
    return 1.0f / (1.0f + expf(-x));
}

// ---------------- weight stacking ----------------
__global__ void prep_kernel(
    const float* __restrict__ Wi, const float* __restrict__ bi,
    const float* __restrict__ Wo, const float* __restrict__ bo,
    const float* __restrict__ Wu, const float* __restrict__ bu,
    const float* __restrict__ U0i, const float* __restrict__ U1i, const float* __restrict__ bbi,
    const float* __restrict__ U00f, const float* __restrict__ U01f,
    const float* __restrict__ U10f, const float* __restrict__ U11f, const float* __restrict__ bbf,
    const float* __restrict__ U0o, const float* __restrict__ U1o, const float* __restrict__ bbo,
    const float* __restrict__ U0u, const float* __restrict__ U1u, const float* __restrict__ bbu)
{
    int t = blockIdx.x * blockDim.x + threadIdx.x;
    int stride = gridDim.x * blockDim.x;

    // leaf transposed: WLt[k*NPAD_L + n], n = j*3 + g ; g: 0=i,1=o,2=u
    for (int idx = t; idx < EMBED * NPAD_L; idx += stride) {
        int k = idx / NPAD_L, n = idx % NPAD_L;
        float v = 0.0f;
        if (n < 450) {
            int j = n / 3, g = n % 3;
            const float* W = (g == 0) ? Wi : (g == 1) ? Wo : Wu;
            v = W[j * EMBED + k];
        }
        g_WLt[idx] = v;
    }
    // inner: n = j*5 + g ; g: 0=i,1=fl,2=fr,3=o,4=u ; k<150 -> U0, else U1
    for (int idx = t; idx < EMBED * NPAD_U; idx += stride) {
        int k = idx / NPAD_U, n = idx % NPAD_U;
        float v = 0.0f;
        if (n < 750) {
            int j = n / 5, g = n % 5;
            const float* U0; const float* U1;
            switch (g) {
                case 0:  U0 = U0i;  U1 = U1i;  break;
                case 1:  U0 = U00f; U1 = U01f; break;
                case 2:  U0 = U10f; U1 = U11f; break;
                case 3:  U0 = U0o;  U1 = U1o;  break;
                default: U0 = U0u;  U1 = U1u;  break;
            }
            v = (k < HIDDEN) ? U0[j * HIDDEN + k] : U1[j * HIDDEN + (k - HIDDEN)];
            g_WUi[n * EMBED + k] = v;   // row-major copy for warp_level
        }
        g_WUt[idx] = v;
    }
    if (t < 480) {
        float v = 0.0f;
        if (t < 450) {
            int j = t / 3, g = t % 3;
            v = (g == 0) ? bi[j] : (g == 1) ? bo[j] : bu[j];
        }
        g_bLi[t] = v;
    }
    if (t < 800) {
        float v = 0.0f;
        if (t < 750) {
            int j = t / 5, g = t % 5;
            v = (g == 0) ? bbi[j] : (g <= 2) ? bbf[j] : (g == 3) ? bbo[j] : bbu[j];
        }
        g_bUi[t] = v;
    }
}

// ---------------- fused tiled GEMM + activation (double-buffered, no div/mod in loop) --------
// thread tile: ROWS rows x 1 j x GATES gates. Requires M % BM == 0.
template<int GATES, int MODE, int BM, int BJ, int ROWS>
__global__ __launch_bounds__((BM / ROWS) * BJ)
void fused_level(int s, int M,
                 const float* __restrict__ emb,
                 const int* __restrict__ words)
{
    constexpr int THREADS = (BM / ROWS) * BJ;
    constexpr int WCOLS = BJ * GATES;
    constexpr int NTOTP = (MODE == 0) ? NPAD_L : NPAD_U;
    constexpr int AELEMS = BM * BK;
    constexpr int WELEMS = WCOLS * BK;
    constexpr int LA = (AELEMS + THREADS - 1) / THREADS;
    constexpr int LW = (WELEMS + THREADS - 1) / THREADS;
    static_assert(LA * THREADS < 2 * AELEMS, "A wrap-around requires <2x overshoot");
    static_assert(LW * THREADS < 2 * WELEMS, "W wrap-around requires <2x overshoot");
    constexpr int NT = EMBED / BK;     // 15 k-tiles

    __shared__ float As[2][BK][BM];
    __shared__ float Ws[2][BK][WCOLS];
    __shared__ int   rowOff[BM];

    const float* __restrict__ WT    = (MODE == 0) ? g_WLt : g_WUt;
    const float* __restrict__ Abase = (MODE == 0) ? emb : (g_H + (2 * s + 1) * HIDDEN);
    const float* __restrict__ bias  = (MODE == 0) ? g_bLi : g_bUi;

    int bm = blockIdx.x * BM;
    int j0 = blockIdx.y * BJ;
    int n0 = j0 * GATES;
    int tid = threadIdx.x;
    int tx = tid % BJ, ty = tid / BJ;

    for (int e = tid; e < BM; e += THREADS) {
        int m = bm + e;
        rowOff[e] = (MODE == 0) ? words[LEAF_START + m] * EMBED : m * EMBED;
    }
    __syncthreads();

    // ---- precomputed index tables (all div/mod done once) ----
    int aGOff[LA], aSOff[LA];
    #pragma unroll
    for (int l = 0; l < LA; l++) {
        int e = tid + l * THREADS;
        if (e >= AELEMS) e -= AELEMS;
        int ml = e / BK, kk = e % BK;
        aGOff[l] = rowOff[ml] + kk;      // + k0 per tile
        aSOff[l] = kk * BM + ml;         // element offset within As buffer
    }
    int wGOff[LW], wSOff[LW];
    #pragma unroll
    for (int l = 0; l < LW; l++) {
        int e = tid + l * THREADS;
        if (e >= WELEMS) e -= WELEMS;
        int kk = e / WCOLS, nl = e % WCOLS;
        wGOff[l] = kk * NTOTP + n0 + nl; // + k0*NTOTP per tile
        wSOff[l] = kk * WCOLS + nl;
    }

    float* AsF = &As[0][0][0];
    float* WsF = &Ws[0][0][0];
    constexpr int ABUF = BK * BM;
    constexpr int WBUF = BK * WCOLS;

    float ra[LA], rw[LW];
    auto fetch = [&](int k0) {
        #pragma unroll
        for (int l = 0; l < LA; l++) ra[l] = Abase[aGOff[l] + k0];
        int wk = k0 * NTOTP;
        #pragma unroll
        for (int l = 0; l < LW; l++) rw[l] = WT[wGOff[l] + wk];
    };
    auto stage = [&](int boff_a, int boff_w) {
        #pragma unroll
        for (int l = 0; l < LA; l++) AsF[boff_a + aSOff[l]] = ra[l];
        #pragma unroll
        for (int l = 0; l < LW; l++) WsF[boff_w + wSOff[l]] = rw[l];
    };

    float acc[ROWS][GATES];
    #pragma unroll
    for (int i = 0; i < ROWS; i++)
        #pragma unroll
        for (int g = 0; g < GATES; g++)
            acc[i][g] = 0.0f;

    fetch(0);
    stage(0, 0);
    __syncthreads();

    #pragma unroll 1
    for (int t = 0; t < NT; t++) {
        int b = t & 1;
        if (t + 1 < NT) fetch((t + 1) * BK);

        const float* Ab = AsF + b * ABUF;
        const float* Wb = WsF + b * WBUF;
        #pragma unroll
        for (int kk = 0; kk < BK; kk++) {
            float a[ROWS], w[GATES];
            if (ROWS == 4) {
                float4 av = *reinterpret_cast<const float4*>(Ab + kk * BM + ty * 4);
                a[0] = av.x; a[1] = av.y; a[2] = av.z; a[3] = av.w;
            } else if (ROWS == 2) {
                float2 av = *reinterpret_cast<const float2*>(Ab + kk * BM + ty * 2);
                a[0] = av.x; a[1] = av.y;
            } else {
                #pragma unroll
                for (int i = 0; i < ROWS; i++) a[i] = Ab[kk * BM + ty * ROWS + i];
            }
            #pragma unroll
            for (int g = 0; g < GATES; g++) w[g] = Wb[kk * WCOLS + tx * GATES + g];
            #pragma unroll
            for (int i = 0; i < ROWS; i++)
                #pragma unroll
                for (int g = 0; g < GATES; g++)
                    acc[i][g] += a[i] * w[g];
        }
        if (t + 1 < NT) stage((b ^ 1) * ABUF, (b ^ 1) * WBUF);
        __syncthreads();
    }

    int j = j0 + tx;
    if (j >= HIDDEN) return;
    int nb = j * GATES;
    #pragma unroll
    for (int i = 0; i < ROWS; i++) {
        int m = bm + ty * ROWS + i;
        if (MODE == 0) {
            float ig = sigmoidf(acc[i][0] + bias[nb + 0]);
            float og = sigmoidf(acc[i][1] + bias[nb + 1]);
            float uv = tanhf   (acc[i][2] + bias[nb + 2]);
            float c = ig * uv;
            float h = og * tanhf(c);
            int node = LEAF_START + m;
            g_H[node * HIDDEN + j] = h;
            g_C[node * HIDDEN + j] = c;
        } else {
            float ig = sigmoidf(acc[i][0] + bias[nb + 0]);
            float fl = sigmoidf(acc[i][1] + bias[nb + 1]);
            float fr = sigmoidf(acc[i][2] + bias[nb + 2]);
            float og = sigmoidf(acc[i][3] + bias[nb + 3]);
            float uv = tanhf   (acc[i][4] + bias[nb + 4]);
            int node = s + m;
            float lc = g_C[(2 * node + 1) * HIDDEN + j];
            float rc = g_C[(2 * node + 2) * HIDDEN + j];
            float c = ig * uv + fl * lc + fr * rc;
            float h = og * tanhf(c);
            g_H[node * HIDDEN + j] = h;
            g_C[node * HIDDEN + j] = c;
        }
    }
}

// ---------------- warp-per-(node, j) kernel for tiny levels ----------------
__global__ void warp_level(int s, int M)
{
    int wid  = (blockIdx.x * blockDim.x + threadIdx.x) >> 5;
    int lane = threadIdx.x & 31;
    int m = wid / HIDDEN;
    int j = wid % HIDDEN;
    if (m >= M) return;

    const float* __restrict__ A  = g_H + (2 * s + 1 + 2 * m) * HIDDEN;  // 300 contiguous
    const float* __restrict__ Wr = g_WUi + (j * 5) * EMBED;

    float a0 = 0.f, a1 = 0.f, a2 = 0.f, a3 = 0.f, a4 = 0.f;
    #pragma unroll
    for (int kb = 0; kb < EMBED; kb += 32) {
        int k = kb + lane;
        float a = A[k];
        a0 += a * Wr[k];
        a1 += a * Wr[EMBED + k];
        a2 += a * Wr[2 * EMBED + k];
        a3 += a * Wr[3 * EMBED + k];
        a4 += a * Wr[4 * EMBED + k];
    }
    #pragma unroll
    for (int d = 16; d > 0; d >>= 1) {
        a0 += __shfl_xor_sync(0xffffffff, a0, d);
        a1 += __shfl_xor_sync(0xffffffff, a1, d);
        a2 += __shfl_xor_sync(0xffffffff, a2, d);
        a3 += __shfl_xor_sync(0xffffffff, a3, d);
        a4 += __shfl_xor_sync(0xffffffff, a4, d);
    }
    if (lane == 0) {
        int nb = j * 5;
        float ig = sigmoidf(a0 + g_bUi[nb + 0]);
        float fl = sigmoidf(a1 + g_bUi[nb + 1]);
        float fr = sigmoidf(a2 + g_bUi[nb + 2]);
        float og = sigmoidf(a3 + g_bUi[nb + 3]);
        float uv = tanhf   (a4 + g_bUi[nb + 4]);
        int node = s + m;
        float lc = g_C[(2 * node + 1) * HIDDEN + j];
        float rc = g_C[(2 * node + 2) * HIDDEN + j];
        float c = ig * uv + fl * lc + fr * rc;
        float h = og * tanhf(c);
        g_H[node * HIDDEN + j] = h;
        g_C[node * HIDDEN + j] = c;
    }
}

// ---------------- loss ----------------
__global__ void zero_out(float* out)
{
    if (threadIdx.x == 0 && blockIdx.x == 0) out[0] = 0.0f;
}

__global__ void loss_kernel(const float* __restrict__ Why,
                            const float* __restrict__ by,
                            const int*   __restrict__ scores,
                            float* __restrict__ out)
{
    int gw   = (blockIdx.x * blockDim.x + threadIdx.x) >> 5;
    int lane = threadIdx.x & 31;
    if (gw >= NN) return;

    const float* h = g_H + gw * HIDDEN;
    float logits[OUTC];
    #pragma unroll
    for (int o = 0; o < OUTC; o++) {
        float sacc = 0.0f;
        for (int k = lane; k < HIDDEN; k += 32)
            sacc += Why[o * HIDDEN + k] * h[k];
        #pragma unroll
        for (int d = 16; d > 0; d >>= 1)
            sacc += __shfl_xor_sync(0xffffffff, sacc, d);
        logits[o] = sacc + by[o];
    }
    if (lane == 0) {
        float mx = logits[0];
        #pragma unroll
        for (int o = 1; o < OUTC; o++) mx = fmaxf(mx, logits[o]);
        float se = 0.0f;
        #pragma unroll
        for (int o = 0; o < OUTC; o++) se += expf(logits[o] - mx);
        float lse = mx + logf(se);
        int sc = scores[gw];
        atomicAdd(out, lse - logits[sc]);
    }
}

// ---------------- launch ----------------
extern "C" void kernel_launch(void* const* d_in, const int* in_sizes, int n_in,
                              void* d_out, int out_size)
{
    const float* Wi   = (const float*)d_in[0];
    const float* bi   = (const float*)d_in[1];
    const float* Wo   = (const float*)d_in[2];
    const float* bo   = (const float*)d_in[3];
    const float* Wu   = (const float*)d_in[4];
    const float* bu   = (const float*)d_in[5];
    const float* U0i  = (const float*)d_in[6];
    const float* U1i  = (const float*)d_in[7];
    const float* bbi  = (const float*)d_in[8];
    const float* U00f = (const float*)d_in[9];
    const float* U01f = (const float*)d_in[10];
    const float* U10f = (const float*)d_in[11];
    const float* U11f = (const float*)d_in[12];
    const float* bbf  = (const float*)d_in[13];
    const float* U0o  = (const float*)d_in[14];
    const float* U1o  = (const float*)d_in[15];
    const float* bbo  = (const float*)d_in[16];
    const float* U0u  = (const float*)d_in[17];
    const float* U1u  = (const float*)d_in[18];
    const float* bbu  = (const float*)d_in[19];
    const float* Why  = (const float*)d_in[20];
    const float* by   = (const float*)d_in[21];
    const float* emb  = (const float*)d_in[22];
    const int*   scores = (const int*)d_in[23];
    const int*   words  = (const int*)d_in[24];

    float* out = (float*)d_out;

    zero_out<<<1, 32>>>(out);
    prep_kernel<<<240, 256>>>(Wi, bi, Wo, bo, Wu, bu,
                              U0i, U1i, bbi,
                              U00f, U01f, U10f, U11f, bbf,
                              U0o, U1o, bbo,
                              U0u, U1u, bbu);

    // leaf: M=4096, GATES=3 — BM=32, BJ=16, ROWS=4 (128 thr), grid (128,10)=1280
    {
        dim3 grid(LL / 32, (HIDDEN + 15) / 16);
        fused_level<3, 0, 32, 16, 4><<<grid, 128>>>(0, LL, emb, words);
    }

    // d=11..8: BM=32, BJ=16, ROWS=4 (128 thr) — grids 640, 320, 160, 80
    for (int d = 11; d >= 8; d--) {
        int s = (1 << d) - 1, M = 1 << d;
        dim3 grid(M / 32, (HIDDEN + 15) / 16);
        fused_level<5, 1, 32, 16, 4><<<grid, 128>>>(s, M, nullptr, nullptr);
    }

    // d=7,6: BM=16, BJ=16, ROWS=2 (128 thr) — grids 80 / 40
    for (int d = 7; d >= 6; d--) {
        int s = (1 << d) - 1, M = 1 << d;
        dim3 grid(M / 16, (HIDDEN + 15) / 16);
        fused_level<5, 1, 16, 16, 2><<<grid, 128>>>(s, M, nullptr, nullptr);
    }

    // d=5..0: warp per (node, j)
    for (int d = 5; d >= 0; d--) {
        int s = (1 << d) - 1, M = 1 << d;
        int warps = M * HIDDEN;
        int blocks = (warps + 7) / 8;
        warp_level<<<blocks, 256>>>(s, M);
    }

    // final loss over all 8191 nodes
    {
        int blocks = (NN + 7) / 8;
        loss_kernel<<<blocks, 256>>>(Why, by, scores, out);
    }
    (void)in_sizes; (void)n_in; (void)out_size;
}